// round 14
// baseline (speedup 1.0000x reference)
#include <cuda_runtime.h>
#include <cuda_bf16.h>
#include <cstdint>

// Problem dims (fixed by the dataset)
#define B_  8
#define N_  10000
#define E_  160000
#define F_  128
#define H_  256
#define NG  (B_ * N_)   // 80000 total nodes
#define NE  (B_ * E_)   // 1280000 total edges
#define SCAN_BLK 256
#define NBLK ((NG + SCAN_BLK - 1) / SCAN_BLK)   // 313

// chunking for the 2-stage row pipeline
#define GCHUNK   40000     // gather chunk (batch boundary: 4 batches)
#define G1SPLIT  40064     // GEMM1 row split (313 / 312 tiles)
#define G2SPLIT  39936     // GEMM2/3 row split (312 / 313 tiles)

// ---------------- static scratch (no allocations allowed) ----------------
__device__ __align__(16) float          g_xw [NG * F_];       // x @ Wc (fp32, for gather)
__device__ __align__(16) __nv_bfloat16  g_x0p[NG * 2 * F_];   // x0 split [hi|lo]
__device__ __align__(16) __nv_bfloat16  g_xrp[NG * 2 * F_];   // xres split [hi|lo]
__device__ __align__(16) __nv_bfloat16  g_h1p[NG * 2 * H_];   // h1 split [hi|lo]
// weights transposed+split (tripled): B'[n][k'] with k' = [hi(K)|lo(K)|hi(K)]
__device__ __align__(16) __nv_bfloat16  g_wcp[F_ * 3 * F_];
__device__ __align__(16) __nv_bfloat16  g_w1p[H_ * 3 * F_];
__device__ __align__(16) __nv_bfloat16  g_w2p[H_ * 3 * H_];

__device__ int   g_cnt [NG];
__device__ float g_dinv[NG];
__device__ int   g_off [NG + 1];
__device__ int   g_cur [NG];
__device__ int   g_esrc[NE];
__device__ int   g_bsum[NBLK];
__device__ int   g_boff[NBLK];
__device__ int   g_is64;

// ================= helpers =================
__device__ __forceinline__ uint32_t smem_u32(const void* p) {
    uint32_t a;
    asm("{ .reg .u64 t; cvta.to.shared.u64 t, %1; cvt.u32.u64 %0, t; }" : "=r"(a) : "l"(p));
    return a;
}
__device__ __forceinline__ void cp16(uint32_t dst, const void* src) {
    asm volatile("cp.async.cg.shared.global [%0], [%1], 16;" :: "r"(dst), "l"(src) : "memory");
}
__device__ __forceinline__ void cpcommit() {
    asm volatile("cp.async.commit_group;" ::: "memory");
}
template <int Nw> __device__ __forceinline__ void cpwait() {
    asm volatile("cp.async.wait_group %0;" :: "n"(Nw) : "memory");
}
__device__ __forceinline__ void ldm4(uint32_t* r, uint32_t addr) {
    asm volatile("ldmatrix.sync.aligned.m8n8.x4.shared.b16 {%0,%1,%2,%3}, [%4];"
        : "=r"(r[0]), "=r"(r[1]), "=r"(r[2]), "=r"(r[3]) : "r"(addr));
}
__device__ __forceinline__ void mma_bf16(float* c, const uint32_t* a, uint32_t b0, uint32_t b1) {
    asm volatile(
        "mma.sync.aligned.m16n8k16.row.col.f32.bf16.bf16.f32 "
        "{%0,%1,%2,%3}, {%4,%5,%6,%7}, {%8,%9}, {%0,%1,%2,%3};"
        : "+f"(c[0]), "+f"(c[1]), "+f"(c[2]), "+f"(c[3])
        : "r"(a[0]), "r"(a[1]), "r"(a[2]), "r"(a[3]), "r"(b0), "r"(b1));
}
__device__ __forceinline__ uint32_t pack_bf2(__nv_bfloat16 a, __nv_bfloat16 b) {
    __nv_bfloat162 h2(a, b);
    return *reinterpret_cast<uint32_t*>(&h2);
}
__device__ __forceinline__ void split1(float v, __nv_bfloat16& h, __nv_bfloat16& l) {
    h = __float2bfloat16(v);
    l = __float2bfloat16(v - __bfloat162float(h));
}

// ---------------- init (zero cnt + dtype flag) ----------------
__global__ void init_kernel() {
    int i = blockIdx.x * blockDim.x + threadIdx.x;
    if (i < NG) g_cnt[i] = 0;
    if (i == 0) g_is64 = 1;
}
__global__ void detect_kernel(const unsigned* __restrict__ w) {
    int i = blockIdx.x * blockDim.x + threadIdx.x;
    if (i < NE && w[2 * i + 1] != 0u) g_is64 = 0;
}

// ---------------- CSR construction ----------------
__device__ __forceinline__ int load_edge(const void* eiv, size_t pos) {
    if (g_is64) return (int)((const long long*)eiv)[pos];
    return ((const int*)eiv)[pos];
}
__global__ void count_kernel(const void* __restrict__ eiv) {
    int idx = blockIdx.x * blockDim.x + threadIdx.x;
    if (idx >= NE) return;
    int b = idx / E_;
    int e = idx - b * E_;
    int dst = load_edge(eiv, (size_t)b * 2 * E_ + E_ + e);
    atomicAdd(&g_cnt[b * N_ + dst], 1);
}

// ---- 3-phase chip-wide scan ----
__global__ __launch_bounds__(SCAN_BLK) void scan1_kernel() {
    __shared__ int sh[SCAN_BLK];
    int i = blockIdx.x * SCAN_BLK + threadIdx.x;
    int tid = threadIdx.x;
    int c = (i < NG) ? g_cnt[i] : 0;
    sh[tid] = c;
    __syncthreads();
    int pref = c;
#pragma unroll
    for (int off = 1; off < SCAN_BLK; off <<= 1) {
        int v = (tid >= off) ? sh[tid - off] : 0;
        __syncthreads();
        pref += v;
        sh[tid] = pref;
        __syncthreads();
    }
    if (i < NG) {
        g_off[i]  = pref - c;
        g_dinv[i] = rsqrtf((float)(c + 1));
    }
    if (tid == SCAN_BLK - 1) g_bsum[blockIdx.x] = pref;
}
__global__ __launch_bounds__(512) void scan2_kernel() {
    __shared__ int sh[512];
    int tid = threadIdx.x;
    int v = (tid < NBLK) ? g_bsum[tid] : 0;
    sh[tid] = v;
    __syncthreads();
    int pref = v;
#pragma unroll
    for (int off = 1; off < 512; off <<= 1) {
        int u = (tid >= off) ? sh[tid - off] : 0;
        __syncthreads();
        pref += u;
        sh[tid] = pref;
        __syncthreads();
    }
    if (tid < NBLK) g_boff[tid] = pref - v;
    if (tid == NBLK - 1) g_off[NG] = pref;
}
__global__ __launch_bounds__(SCAN_BLK) void scan3_kernel() {
    int i = blockIdx.x * SCAN_BLK + threadIdx.x;
    if (i >= NG) return;
    int o = g_off[i] + g_boff[blockIdx.x];
    g_off[i] = o;
    g_cur[i] = o;
}

__global__ void fill_kernel(const void* __restrict__ eiv) {
    int idx = blockIdx.x * blockDim.x + threadIdx.x;
    if (idx >= NE) return;
    int b = idx / E_;
    int e = idx - b * E_;
    size_t base = (size_t)b * 2 * E_;
    int src = load_edge(eiv, base + e);
    int dst = load_edge(eiv, base + E_ + e);
    int pos = atomicAdd(&g_cur[b * N_ + dst], 1);
    g_esrc[pos] = b * N_ + src;
}

// ---------------- x0 split [hi(F) | lo(F)] per row -------------------------
__global__ void split_x0_kernel(const float* __restrict__ x0) {
    int i = blockIdx.x * blockDim.x + threadIdx.x;   // over NG*F/4
    if (i >= NG * F_ / 4) return;
    int row = i >> 5;
    int col = (i & 31) * 4;
    float4 v = ((const float4*)x0)[i];
    __nv_bfloat16 h0, h1, h2, h3, l0, l1, l2, l3;
    split1(v.x, h0, l0); split1(v.y, h1, l1); split1(v.z, h2, l2); split1(v.w, h3, l3);
    uint2 hw = make_uint2(pack_bf2(h0, h1), pack_bf2(h2, h3));
    uint2 lw = make_uint2(pack_bf2(l0, l1), pack_bf2(l2, l3));
    size_t base = (size_t)row * (2 * F_) + col;
    *(uint2*)&g_x0p[base]      = hw;
    *(uint2*)&g_x0p[base + F_] = lw;
}

// ---------------- all three weight transposes+splits in ONE kernel ---------
__global__ void wsplit_all_kernel(const float* __restrict__ Wc,
                                  const float* __restrict__ W1,
                                  const float* __restrict__ W2) {
    int i = blockIdx.x * blockDim.x + threadIdx.x;
    const int n0 = F_ * F_;
    const int n1 = F_ * H_;
    const int n2 = H_ * H_;
    const float* W; __nv_bfloat16* T; int K, idx;
    if (i < n0)                { W = Wc; T = g_wcp; K = F_; idx = i; }
    else if (i < n0 + n1)      { W = W1; T = g_w1p; K = F_; idx = i - n0; }
    else if (i < n0 + n1 + n2) { W = W2; T = g_w2p; K = H_; idx = i - n0 - n1; }
    else return;
    int Nn = (T == g_wcp) ? F_ : H_;
    int n = idx / K, k = idx - n * K;
    float v = W[(size_t)k * Nn + n];
    __nv_bfloat16 h, l;
    split1(v, h, l);
    size_t base = (size_t)n * (3 * K);
    T[base + k]         = h;
    T[base + K + k]     = l;
    T[base + 2 * K + k] = h;
}

// ---------------- aggregation gather (warp per destination node) -----------
// processes nodes [node0, node0 + GCHUNK)
__global__ __launch_bounds__(256) void gather_kernel(const float* __restrict__ x0,
                                                     const float* __restrict__ bc,
                                                     int node0) {
    int warp = node0 + ((blockIdx.x * blockDim.x + threadIdx.x) >> 5);
    int lane = threadIdx.x & 31;
    if (warp >= node0 + GCHUNK) return;

    const float4* xw4 = (const float4*)g_xw;
    float di = g_dinv[warp];

    float4 v  = xw4[(size_t)warp * 32 + lane];
    float  w0 = di * di;
    float4 acc;
    acc.x = w0 * v.x; acc.y = w0 * v.y; acc.z = w0 * v.z; acc.w = w0 * v.w;

    int e0 = g_off[warp], e1 = g_off[warp + 1];
    for (int e = e0; e < e1; e++) {
        int   s = g_esrc[e];
        float w = di * g_dinv[s];
        float4 u = xw4[(size_t)s * 32 + lane];
        acc.x += w * u.x; acc.y += w * u.y; acc.z += w * u.z; acc.w += w * u.w;
    }

    float4 b4 = ((const float4*)bc)[lane];
    float4 r4 = ((const float4*)x0)[(size_t)warp * 32 + lane];
    float o0 = fmaxf(acc.x + b4.x, 0.f) + r4.x;
    float o1 = fmaxf(acc.y + b4.y, 0.f) + r4.y;
    float o2 = fmaxf(acc.z + b4.z, 0.f) + r4.z;
    float o3 = fmaxf(acc.w + b4.w, 0.f) + r4.w;

    __nv_bfloat16 h0, h1, h2, h3, l0, l1, l2, l3;
    split1(o0, h0, l0); split1(o1, h1, l1); split1(o2, h2, l2); split1(o3, h3, l3);
    uint2 hw = make_uint2(pack_bf2(h0, h1), pack_bf2(h2, h3));
    uint2 lw = make_uint2(pack_bf2(l0, l1), pack_bf2(l2, l3));
    size_t base = (size_t)warp * (2 * F_) + lane * 4;
    *(uint2*)&g_xrp[base]      = hw;
    *(uint2*)&g_xrp[base + F_] = lw;
}

// ================= HMMA bf16 GEMM: k-chunk 64, 3-stage cp.async ============
#define ROWB_   144
#define A_BYTES_ (128 * ROWB_)      // 18432
#define STAGE_B_ (256 * ROWB_)      // 36864
#define SMEM_TOT_ (3 * STAGE_B_)    // 110592

template <int EPI>
__global__ __launch_bounds__(256) void gemm_bf16(
    const __nv_bfloat16* __restrict__ Ap, const __nv_bfloat16* __restrict__ Bp,
    const float* __restrict__ bias, float* __restrict__ Cf,
    __nv_bfloat16* __restrict__ Cbf, int Nn, int Ka, int mrow0)
{
    extern __shared__ __align__(16) char smem[];
    const int tid  = threadIdx.x;
    const int w    = tid >> 5;
    const int lane = tid & 31;
    const int m0 = mrow0 + blockIdx.y * 128;
    const int n0 = blockIdx.x * 128;
    const int m0w = (w >> 2) * 64;
    const int n0w = (w & 3) * 32;

    const uint32_t sb = smem_u32(smem);
    const int Kp = 3 * Ka;
    const int As = 2 * Ka;

    float acc[4][4][4];
#pragma unroll
    for (int a = 0; a < 4; a++)
#pragma unroll
        for (int b = 0; b < 4; b++)
#pragma unroll
            for (int q = 0; q < 4; q++) acc[a][b][q] = 0.f;

    const int grp = lane >> 3, lr = lane & 7;
    const uint32_t aSel = (uint32_t)((m0w + (grp & 1) * 8 + lr) * ROWB_ + (grp >> 1) * 16);
    const uint32_t bSel = (uint32_t)((n0w + ((grp >> 1) & 1) * 8 + lr) * ROWB_ + (grp & 1) * 16);

    const int nk = Kp >> 6;

#define PREFETCH(kc, st)                                                          \
    {                                                                             \
        const int k0_ = (kc) << 6;                                                \
        const int ak_ = (k0_ < Ka) ? k0_ : k0_ - Ka;                              \
        _Pragma("unroll")                                                         \
        for (int i_ = 0; i_ < 4; i_++) {                                          \
            int c_ = tid + i_ * 256;                                              \
            int row_ = c_ >> 3, q_ = (c_ & 7) * 8;                                \
            cp16(sb + (st) * STAGE_B_ + row_ * ROWB_ + q_ * 2,                    \
                 Ap + (size_t)(m0 + row_) * As + ak_ + q_);                       \
            cp16(sb + (st) * STAGE_B_ + A_BYTES_ + row_ * ROWB_ + q_ * 2,         \
                 Bp + (size_t)(n0 + row_) * Kp + k0_ + q_);                       \
        }                                                                         \
        cpcommit();                                                               \
    }

    PREFETCH(0, 0);
    PREFETCH(1, 1);

    for (int kc = 0; kc < nk; kc++) {
        const int st = kc % 3;
        if (kc + 2 < nk)      { const int s2 = (kc + 2) % 3; PREFETCH(kc + 2, s2); cpwait<2>(); }
        else if (kc + 1 < nk) { cpwait<1>(); }
        else                  { cpwait<0>(); }
        __syncthreads();

        const uint32_t aBase = sb + st * STAGE_B_ + aSel;
        const uint32_t bBase = sb + st * STAGE_B_ + A_BYTES_ + bSel;
#pragma unroll
        for (int ks = 0; ks < 4; ks++) {
            uint32_t a[4][4], b[2][4];
#pragma unroll
            for (int mi = 0; mi < 4; mi++)
                ldm4(a[mi], aBase + mi * 16 * ROWB_ + ks * 32);
#pragma unroll
            for (int nj = 0; nj < 2; nj++)
                ldm4(b[nj], bBase + nj * 16 * ROWB_ + ks * 32);
#pragma unroll
            for (int mi = 0; mi < 4; mi++)
#pragma unroll
                for (int nf = 0; nf < 4; nf++)
                    mma_bf16(acc[mi][nf], a[mi],
                             b[nf >> 1][(nf & 1) * 2], b[nf >> 1][(nf & 1) * 2 + 1]);
        }
        __syncthreads();
    }
#undef PREFETCH

    const int r0 = lane >> 2;
    const int cc = (lane & 3) * 2;
    const int rs = 2 * Nn;
#pragma unroll
    for (int mi = 0; mi < 4; mi++) {
        const int row1 = m0 + m0w + mi * 16 + r0;
        const int row2 = row1 + 8;
#pragma unroll
        for (int nf = 0; nf < 4; nf++) {
            const int col = n0 + n0w + nf * 8 + cc;
            float v0 = acc[mi][nf][0], v1 = acc[mi][nf][1];
            float v2 = acc[mi][nf][2], v3 = acc[mi][nf][3];
            if (EPI >= 1) {
                float bb0 = bias[col], bb1 = bias[col + 1];
                v0 += bb0; v1 += bb1; v2 += bb0; v3 += bb1;
                v0 = (v0 > 0.f) ? v0 : 0.01f * v0;
                v1 = (v1 > 0.f) ? v1 : 0.01f * v1;
                v2 = (v2 > 0.f) ? v2 : 0.01f * v2;
                v3 = (v3 > 0.f) ? v3 : 0.01f * v3;
            }
            if (EPI == 1) {
                __nv_bfloat16 h0, h1, h2, h3, l0, l1, l2, l3;
                split1(v0, h0, l0); split1(v1, h1, l1);
                split1(v2, h2, l2); split1(v3, h3, l3);
                size_t b1a = (size_t)row1 * rs + col;
                size_t b2a = (size_t)row2 * rs + col;
                *(uint32_t*)&Cbf[b1a]      = pack_bf2(h0, h1);
                *(uint32_t*)&Cbf[b1a + Nn] = pack_bf2(l0, l1);
                *(uint32_t*)&Cbf[b2a]      = pack_bf2(h2, h3);
                *(uint32_t*)&Cbf[b2a + Nn] = pack_bf2(l2, l3);
            } else {
                *(float2*)&Cf[(size_t)row1 * Nn + col] = make_float2(v0, v1);
                *(float2*)&Cf[(size_t)row2 * Nn + col] = make_float2(v2, v3);
            }
        }
    }
}

// ---------------- launch ----------------
extern "C" void kernel_launch(void* const* d_in, const int* in_sizes, int n_in,
                              void* d_out, int out_size) {
    const float* x0  = (const float*)d_in[0];   // [B,N,F]
    const void*  ei  = d_in[1];                 // [B,2,E] int32 OR int64
    const float* Wc  = (const float*)d_in[2];   // [F,F]
    const float* bc  = (const float*)d_in[3];   // [F]
    const float* W1  = (const float*)d_in[4];   // [F,H]
    const float* b1  = (const float*)d_in[5];   // [H]
    const float* W2  = (const float*)d_in[6];   // [H,H]
    const float* b2  = (const float*)d_in[7];   // [H]
    float*       out = (float*)d_out;           // [B,N,H]

    float* p_xw;
    __nv_bfloat16 *p_x0p, *p_xrp, *p_h1p, *p_wcp, *p_w1p, *p_w2p;
    cudaGetSymbolAddress((void**)&p_xw,  g_xw);
    cudaGetSymbolAddress((void**)&p_x0p, g_x0p);
    cudaGetSymbolAddress((void**)&p_xrp, g_xrp);
    cudaGetSymbolAddress((void**)&p_h1p, g_h1p);
    cudaGetSymbolAddress((void**)&p_wcp, g_wcp);
    cudaGetSymbolAddress((void**)&p_w1p, g_w1p);
    cudaGetSymbolAddress((void**)&p_w2p, g_w2p);

    cudaFuncSetAttribute(gemm_bf16<0>, cudaFuncAttributeMaxDynamicSharedMemorySize, SMEM_TOT_);
    cudaFuncSetAttribute(gemm_bf16<1>, cudaFuncAttributeMaxDynamicSharedMemorySize, SMEM_TOT_);
    cudaFuncSetAttribute(gemm_bf16<2>, cudaFuncAttributeMaxDynamicSharedMemorySize, SMEM_TOT_);

    // persistent side stream + events (host resources, created once)
    static cudaStream_t s_side = nullptr;
    static cudaEvent_t  s_fork = nullptr, s_e1a = nullptr, s_e1b = nullptr,
                        s_eg0 = nullptr, s_eg1 = nullptr;
    if (!s_side) {
        cudaStreamCreateWithFlags(&s_side, cudaStreamNonBlocking);
        cudaEventCreateWithFlags(&s_fork, cudaEventDisableTiming);
        cudaEventCreateWithFlags(&s_e1a,  cudaEventDisableTiming);
        cudaEventCreateWithFlags(&s_e1b,  cudaEventDisableTiming);
        cudaEventCreateWithFlags(&s_eg0,  cudaEventDisableTiming);
        cudaEventCreateWithFlags(&s_eg1,  cudaEventDisableTiming);
    }

    // ---- fork: CSR chain on side stream ----
    cudaEventRecord(s_fork, 0);
    cudaStreamWaitEvent(s_side, s_fork, 0);

    init_kernel  <<<(NG + 255) / 256, 256, 0, s_side>>>();
    detect_kernel<<<(NE + 255) / 256, 256, 0, s_side>>>((const unsigned*)ei);
    count_kernel <<<(NE + 255) / 256, 256, 0, s_side>>>(ei);
    scan1_kernel <<<NBLK, SCAN_BLK, 0, s_side>>>();
    scan2_kernel <<<1, 512, 0, s_side>>>();
    scan3_kernel <<<NBLK, SCAN_BLK, 0, s_side>>>();
    fill_kernel  <<<(NE + 255) / 256, 256, 0, s_side>>>(ei);

    // ---- main stream: operand prep + GEMM1 in two row chunks ----
    split_x0_kernel<<<(NG * F_ / 4 + 255) / 256, 256>>>(x0);
    {
        int tot = F_ * F_ + F_ * H_ + H_ * H_;
        wsplit_all_kernel<<<(tot + 255) / 256, 256>>>(Wc, W1, W2);
    }
    // GEMM1 c0: rows [0, 40064)  (313 tiles) — covers gather c0 sources
    {
        dim3 grid(1, G1SPLIT / 128);
        gemm_bf16<0><<<grid, 256, SMEM_TOT_>>>(p_x0p, p_wcp, nullptr, p_xw, nullptr, F_, F_, 0);
    }
    cudaEventRecord(s_e1a, 0);
    // GEMM1 c1: rows [40064, 80000)  (312 tiles)
    {
        dim3 grid(1, (NG - G1SPLIT) / 128);
        gemm_bf16<0><<<grid, 256, SMEM_TOT_>>>(p_x0p, p_wcp, nullptr, p_xw, nullptr, F_, F_, G1SPLIT);
    }
    cudaEventRecord(s_e1b, 0);

    // ---- side stream: gathers (CSR done in-stream; xw via events) ----
    cudaStreamWaitEvent(s_side, s_e1a, 0);
    gather_kernel<<<GCHUNK / 8, 256, 0, s_side>>>(x0, bc, 0);
    cudaEventRecord(s_eg0, s_side);
    cudaStreamWaitEvent(s_side, s_e1b, 0);
    gather_kernel<<<GCHUNK / 8, 256, 0, s_side>>>(x0, bc, GCHUNK);
    cudaEventRecord(s_eg1, s_side);

    // ---- main stream: GEMM2 / GEMM3 in matching row chunks ----
    // GEMM2 c0: rows [0, 39936) (312 tiles) — needs gather c0 only
    cudaStreamWaitEvent(0, s_eg0, 0);
    {
        dim3 grid(H_ / 128, G2SPLIT / 128);
        gemm_bf16<1><<<grid, 256, SMEM_TOT_>>>(p_xrp, p_w1p, b1, nullptr, p_h1p, H_, F_, 0);
    }
    // GEMM3 c0: rows [0, 39936) — needs h1 c0 (same stream)
    {
        dim3 grid(H_ / 128, G2SPLIT / 128);
        gemm_bf16<2><<<grid, 256, SMEM_TOT_>>>(p_h1p, p_w2p, b2, out, nullptr, H_, H_, 0);
    }
    // GEMM2 c1: rows [39936, 80000) (313 tiles) — needs both gathers
    cudaStreamWaitEvent(0, s_eg1, 0);
    {
        dim3 grid(H_ / 128, (NG - G2SPLIT) / 128);
        gemm_bf16<1><<<grid, 256, SMEM_TOT_>>>(p_xrp, p_w1p, b1, nullptr, p_h1p, H_, F_, G2SPLIT);
    }
    // GEMM3 c1: rows [39936, 80000)
    {
        dim3 grid(H_ / 128, (NG - G2SPLIT) / 128);
        gemm_bf16<2><<<grid, 256, SMEM_TOT_>>>(p_h1p, p_w2p, b2, out, nullptr, H_, H_, G2SPLIT);
    }
}

// round 15
// speedup vs baseline: 1.7698x; 1.7698x over previous
#include <cuda_runtime.h>
#include <cuda_fp16.h>
#include <cstdint>

// Problem dims (fixed by the dataset)
#define B_  8
#define N_  10000
#define E_  160000
#define F_  128
#define H_  256
#define NG  (B_ * N_)   // 80000 total nodes
#define NE  (B_ * E_)   // 1280000 total edges
#define SCAN_BLK 256
#define NBLK ((NG + SCAN_BLK - 1) / SCAN_BLK)   // 313

// ---------------- static scratch (no allocations allowed) ----------------
__device__ __align__(16) float  g_xw  [NG * F_];   // x @ Wc (fp32, for gather)
__device__ __align__(16) __half g_x016[NG * F_];   // x0 as fp16
__device__ __align__(16) __half g_xr16[NG * F_];   // xres as fp16
__device__ __align__(16) __half g_h116[NG * H_];   // h1 as fp16
// weights transposed to [N][K] fp16: T[n*K+k] = W[k*N+n]
__device__ __align__(16) __half g_wct[F_ * F_];
__device__ __align__(16) __half g_w1t[H_ * F_];
__device__ __align__(16) __half g_w2t[H_ * H_];

__device__ int   g_cnt [NG];
__device__ float g_dinv[NG];
__device__ int   g_off [NG + 1];
__device__ int   g_cur [NG];
__device__ int   g_esrc[NE];
__device__ int   g_bsum[NBLK];
__device__ int   g_boff[NBLK];
__device__ int   g_is64;

// ================= helpers =================
__device__ __forceinline__ uint32_t smem_u32(const void* p) {
    uint32_t a;
    asm("{ .reg .u64 t; cvta.to.shared.u64 t, %1; cvt.u32.u64 %0, t; }" : "=r"(a) : "l"(p));
    return a;
}
__device__ __forceinline__ void cp16(uint32_t dst, const void* src) {
    asm volatile("cp.async.cg.shared.global [%0], [%1], 16;" :: "r"(dst), "l"(src) : "memory");
}
__device__ __forceinline__ void cpcommit() {
    asm volatile("cp.async.commit_group;" ::: "memory");
}
template <int Nw> __device__ __forceinline__ void cpwait() {
    asm volatile("cp.async.wait_group %0;" :: "n"(Nw) : "memory");
}
__device__ __forceinline__ void ldm4(uint32_t* r, uint32_t addr) {
    asm volatile("ldmatrix.sync.aligned.m8n8.x4.shared.b16 {%0,%1,%2,%3}, [%4];"
        : "=r"(r[0]), "=r"(r[1]), "=r"(r[2]), "=r"(r[3]) : "r"(addr));
}
__device__ __forceinline__ void mma_fp16(float* c, const uint32_t* a, uint32_t b0, uint32_t b1) {
    asm volatile(
        "mma.sync.aligned.m16n8k16.row.col.f32.f16.f16.f32 "
        "{%0,%1,%2,%3}, {%4,%5,%6,%7}, {%8,%9}, {%0,%1,%2,%3};"
        : "+f"(c[0]), "+f"(c[1]), "+f"(c[2]), "+f"(c[3])
        : "r"(a[0]), "r"(a[1]), "r"(a[2]), "r"(a[3]), "r"(b0), "r"(b1));
}
__device__ __forceinline__ uint32_t pack_h2(float a, float b) {
    __half2 h = __floats2half2_rn(a, b);
    return *reinterpret_cast<uint32_t*>(&h);
}

// ---------------- init (zero cnt + dtype flag) ----------------
__global__ void init_kernel() {
    int i = blockIdx.x * blockDim.x + threadIdx.x;
    if (i < NG) g_cnt[i] = 0;
    if (i == 0) g_is64 = 1;
}
// single block: checks 1024 64-bit slots; int32 buffer is 2*NE*4 B, so
// 1024*8 B is far in-bounds either way.
__global__ void detect_kernel(const unsigned* __restrict__ w) {
    int i = threadIdx.x;
    if (w[2 * i + 1] != 0u) g_is64 = 0;
}

// ---------------- CSR construction ----------------
__device__ __forceinline__ int load_edge(const void* eiv, size_t pos) {
    if (g_is64) return (int)((const long long*)eiv)[pos];
    return ((const int*)eiv)[pos];
}
__global__ void count_kernel(const void* __restrict__ eiv) {
    int idx = blockIdx.x * blockDim.x + threadIdx.x;
    if (idx >= NE) return;
    int b = idx / E_;
    int e = idx - b * E_;
    int dst = load_edge(eiv, (size_t)b * 2 * E_ + E_ + e);
    atomicAdd(&g_cnt[b * N_ + dst], 1);
}

// ---- 3-phase chip-wide scan ----
__global__ __launch_bounds__(SCAN_BLK) void scan1_kernel() {
    __shared__ int sh[SCAN_BLK];
    int i = blockIdx.x * SCAN_BLK + threadIdx.x;
    int tid = threadIdx.x;
    int c = (i < NG) ? g_cnt[i] : 0;
    sh[tid] = c;
    __syncthreads();
    int pref = c;
#pragma unroll
    for (int off = 1; off < SCAN_BLK; off <<= 1) {
        int v = (tid >= off) ? sh[tid - off] : 0;
        __syncthreads();
        pref += v;
        sh[tid] = pref;
        __syncthreads();
    }
    if (i < NG) {
        g_off[i]  = pref - c;
        g_dinv[i] = rsqrtf((float)(c + 1));
    }
    if (tid == SCAN_BLK - 1) g_bsum[blockIdx.x] = pref;
}
__global__ __launch_bounds__(512) void scan2_kernel() {
    __shared__ int sh[512];
    int tid = threadIdx.x;
    int v = (tid < NBLK) ? g_bsum[tid] : 0;
    sh[tid] = v;
    __syncthreads();
    int pref = v;
#pragma unroll
    for (int off = 1; off < 512; off <<= 1) {
        int u = (tid >= off) ? sh[tid - off] : 0;
        __syncthreads();
        pref += u;
        sh[tid] = pref;
        __syncthreads();
    }
    if (tid < NBLK) g_boff[tid] = pref - v;
    if (tid == NBLK - 1) g_off[NG] = pref;
}
__global__ __launch_bounds__(SCAN_BLK) void scan3_kernel() {
    int i = blockIdx.x * SCAN_BLK + threadIdx.x;
    if (i >= NG) return;
    int o = g_off[i] + g_boff[blockIdx.x];
    g_off[i] = o;
    g_cur[i] = o;
}

__global__ void fill_kernel(const void* __restrict__ eiv) {
    int idx = blockIdx.x * blockDim.x + threadIdx.x;
    if (idx >= NE) return;
    int b = idx / E_;
    int e = idx - b * E_;
    size_t base = (size_t)b * 2 * E_;
    int src = load_edge(eiv, base + e);
    int dst = load_edge(eiv, base + E_ + e);
    int pos = atomicAdd(&g_cur[b * N_ + dst], 1);
    g_esrc[pos] = b * N_ + src;
}

// ---------------- x0 -> fp16 ----------------
__global__ void x0_fp16_kernel(const float* __restrict__ x0) {
    int i = blockIdx.x * blockDim.x + threadIdx.x;   // over NG*F/4
    if (i >= NG * F_ / 4) return;
    float4 v = ((const float4*)x0)[i];
    uint2 o = make_uint2(pack_h2(v.x, v.y), pack_h2(v.z, v.w));
    ((uint2*)g_x016)[i] = o;
}

// ---------------- all three weight transposes -> fp16 [N][K] ---------------
__global__ void wt_all_kernel(const float* __restrict__ Wc,
                              const float* __restrict__ W1,
                              const float* __restrict__ W2) {
    int i = blockIdx.x * blockDim.x + threadIdx.x;
    const int n0 = F_ * F_;
    const int n1 = F_ * H_;
    const int n2 = H_ * H_;
    const float* W; __half* T; int K, Nn, idx;
    if (i < n0)                { W = Wc; T = g_wct; K = F_; Nn = F_; idx = i; }
    else if (i < n0 + n1)      { W = W1; T = g_w1t; K = F_; Nn = H_; idx = i - n0; }
    else if (i < n0 + n1 + n2) { W = W2; T = g_w2t; K = H_; Nn = H_; idx = i - n0 - n1; }
    else return;
    int n = idx / K, k = idx - n * K;
    T[(size_t)n * K + k] = __float2half_rn(W[(size_t)k * Nn + n]);
}

// ---------------- aggregation gather (warp per destination node) -----------
// xres = relu(agg + bc) + x0  -> fp16
__global__ __launch_bounds__(256) void gather_kernel(const float* __restrict__ x0,
                                                     const float* __restrict__ bc) {
    int warp = (blockIdx.x * blockDim.x + threadIdx.x) >> 5;
    int lane = threadIdx.x & 31;
    if (warp >= NG) return;

    const float4* xw4 = (const float4*)g_xw;
    float di = g_dinv[warp];

    float4 v  = xw4[(size_t)warp * 32 + lane];
    float  w0 = di * di;
    float4 acc;
    acc.x = w0 * v.x; acc.y = w0 * v.y; acc.z = w0 * v.z; acc.w = w0 * v.w;

    int e0 = g_off[warp], e1 = g_off[warp + 1];
    for (int e = e0; e < e1; e++) {
        int   s = g_esrc[e];
        float w = di * g_dinv[s];
        float4 u = xw4[(size_t)s * 32 + lane];
        acc.x += w * u.x; acc.y += w * u.y; acc.z += w * u.z; acc.w += w * u.w;
    }

    float4 b4 = ((const float4*)bc)[lane];
    float4 r4 = ((const float4*)x0)[(size_t)warp * 32 + lane];
    float o0 = fmaxf(acc.x + b4.x, 0.f) + r4.x;
    float o1 = fmaxf(acc.y + b4.y, 0.f) + r4.y;
    float o2 = fmaxf(acc.z + b4.z, 0.f) + r4.z;
    float o3 = fmaxf(acc.w + b4.w, 0.f) + r4.w;

    uint2 o = make_uint2(pack_h2(o0, o1), pack_h2(o2, o3));
    ((uint2*)g_xr16)[(size_t)warp * 32 + lane] = o;
}

// ================= HMMA fp16 GEMM: k-chunk 64, 3-stage cp.async ============
// C[M,N] = act(A @ B^T + bias); A [M,K] row-major fp16, B [N,K] row-major
// fp16 (transposed weights). CTA tile 128x128, 8 warps of 64x32, smem row
// stride 144 B (odd 16B multiple -> ldmatrix conflict-free).
// EPI: 0 = fp32 out, no bias; 2 = bias+leaky -> fp32; 3 = bias+leaky -> fp16.
#define ROWB_   144
#define A_BYTES_ (128 * ROWB_)      // 18432
#define STAGE_B_ (256 * ROWB_)      // 36864
#define SMEM_TOT_ (3 * STAGE_B_)    // 110592

template <int EPI>
__global__ __launch_bounds__(256) void gemm_fp16(
    const __half* __restrict__ Ap, const __half* __restrict__ Bp,
    const float* __restrict__ bias, float* __restrict__ Cf,
    __half* __restrict__ Ch, int Nn, int Ka)
{
    extern __shared__ __align__(16) char smem[];
    const int tid  = threadIdx.x;
    const int w    = tid >> 5;
    const int lane = tid & 31;
    const int m0 = blockIdx.y * 128;
    const int n0 = blockIdx.x * 128;
    const int m0w = (w >> 2) * 64;
    const int n0w = (w & 3) * 32;

    const uint32_t sb = smem_u32(smem);

    float acc[4][4][4];
#pragma unroll
    for (int a = 0; a < 4; a++)
#pragma unroll
        for (int b = 0; b < 4; b++)
#pragma unroll
            for (int q = 0; q < 4; q++) acc[a][b][q] = 0.f;

    const int grp = lane >> 3, lr = lane & 7;
    const uint32_t aSel = (uint32_t)((m0w + (grp & 1) * 8 + lr) * ROWB_ + (grp >> 1) * 16);
    const uint32_t bSel = (uint32_t)((n0w + ((grp >> 1) & 1) * 8 + lr) * ROWB_ + (grp & 1) * 16);

    const int nk = Ka >> 6;

#define PREFETCH(kc, st)                                                          \
    {                                                                             \
        const int k0_ = (kc) << 6;                                                \
        _Pragma("unroll")                                                         \
        for (int i_ = 0; i_ < 4; i_++) {                                          \
            int c_ = tid + i_ * 256;                                              \
            int row_ = c_ >> 3, q_ = (c_ & 7) * 8;                                \
            cp16(sb + (st) * STAGE_B_ + row_ * ROWB_ + q_ * 2,                    \
                 Ap + (size_t)(m0 + row_) * Ka + k0_ + q_);                       \
            cp16(sb + (st) * STAGE_B_ + A_BYTES_ + row_ * ROWB_ + q_ * 2,         \
                 Bp + (size_t)(n0 + row_) * Ka + k0_ + q_);                       \
        }                                                                         \
        cpcommit();                                                               \
    }

    PREFETCH(0, 0);
    PREFETCH(1, 1);

    for (int kc = 0; kc < nk; kc++) {
        const int st = kc % 3;
        if (kc + 2 < nk)      { const int s2 = (kc + 2) % 3; PREFETCH(kc + 2, s2); cpwait<2>(); }
        else if (kc + 1 < nk) { cpwait<1>(); }
        else                  { cpwait<0>(); }
        __syncthreads();

        const uint32_t aBase = sb + st * STAGE_B_ + aSel;
        const uint32_t bBase = sb + st * STAGE_B_ + A_BYTES_ + bSel;
#pragma unroll
        for (int ks = 0; ks < 4; ks++) {
            uint32_t a[4][4], b[2][4];
#pragma unroll
            for (int mi = 0; mi < 4; mi++)
                ldm4(a[mi], aBase + mi * 16 * ROWB_ + ks * 32);
#pragma unroll
            for (int nj = 0; nj < 2; nj++)
                ldm4(b[nj], bBase + nj * 16 * ROWB_ + ks * 32);
#pragma unroll
            for (int mi = 0; mi < 4; mi++)
#pragma unroll
                for (int nf = 0; nf < 4; nf++)
                    mma_fp16(acc[mi][nf], a[mi],
                             b[nf >> 1][(nf & 1) * 2], b[nf >> 1][(nf & 1) * 2 + 1]);
        }
        __syncthreads();
    }
#undef PREFETCH

    const int r0 = lane >> 2;
    const int cc = (lane & 3) * 2;
#pragma unroll
    for (int mi = 0; mi < 4; mi++) {
        const int row1 = m0 + m0w + mi * 16 + r0;
        const int row2 = row1 + 8;
#pragma unroll
        for (int nf = 0; nf < 4; nf++) {
            const int col = n0 + n0w + nf * 8 + cc;
            float v0 = acc[mi][nf][0], v1 = acc[mi][nf][1];
            float v2 = acc[mi][nf][2], v3 = acc[mi][nf][3];
            if (EPI >= 2) {
                float bb0 = bias[col], bb1 = bias[col + 1];
                v0 += bb0; v1 += bb1; v2 += bb0; v3 += bb1;
                v0 = (v0 > 0.f) ? v0 : 0.01f * v0;
                v1 = (v1 > 0.f) ? v1 : 0.01f * v1;
                v2 = (v2 > 0.f) ? v2 : 0.01f * v2;
                v3 = (v3 > 0.f) ? v3 : 0.01f * v3;
            }
            if (EPI == 3) {
                *(uint32_t*)&Ch[(size_t)row1 * Nn + col] = pack_h2(v0, v1);
                *(uint32_t*)&Ch[(size_t)row2 * Nn + col] = pack_h2(v2, v3);
            } else {
                *(float2*)&Cf[(size_t)row1 * Nn + col] = make_float2(v0, v1);
                *(float2*)&Cf[(size_t)row2 * Nn + col] = make_float2(v2, v3);
            }
        }
    }
}

// ---------------- launch ----------------
extern "C" void kernel_launch(void* const* d_in, const int* in_sizes, int n_in,
                              void* d_out, int out_size) {
    const float* x0  = (const float*)d_in[0];   // [B,N,F]
    const void*  ei  = d_in[1];                 // [B,2,E] int32 OR int64
    const float* Wc  = (const float*)d_in[2];   // [F,F]
    const float* bc  = (const float*)d_in[3];   // [F]
    const float* W1  = (const float*)d_in[4];   // [F,H]
    const float* b1  = (const float*)d_in[5];   // [H]
    const float* W2  = (const float*)d_in[6];   // [H,H]
    const float* b2  = (const float*)d_in[7];   // [H]
    float*       out = (float*)d_out;           // [B,N,H]

    float* p_xw;
    __half *p_x016, *p_xr16, *p_h116, *p_wct, *p_w1t, *p_w2t;
    cudaGetSymbolAddress((void**)&p_xw,   g_xw);
    cudaGetSymbolAddress((void**)&p_x016, g_x016);
    cudaGetSymbolAddress((void**)&p_xr16, g_xr16);
    cudaGetSymbolAddress((void**)&p_h116, g_h116);
    cudaGetSymbolAddress((void**)&p_wct,  g_wct);
    cudaGetSymbolAddress((void**)&p_w1t,  g_w1t);
    cudaGetSymbolAddress((void**)&p_w2t,  g_w2t);

    cudaFuncSetAttribute(gemm_fp16<0>, cudaFuncAttributeMaxDynamicSharedMemorySize, SMEM_TOT_);
    cudaFuncSetAttribute(gemm_fp16<2>, cudaFuncAttributeMaxDynamicSharedMemorySize, SMEM_TOT_);
    cudaFuncSetAttribute(gemm_fp16<3>, cudaFuncAttributeMaxDynamicSharedMemorySize, SMEM_TOT_);

    // persistent side stream + events (host resources, created once)
    static cudaStream_t s_side = nullptr;
    static cudaEvent_t  s_fork = nullptr, s_join = nullptr;
    if (!s_side) {
        cudaStreamCreateWithFlags(&s_side, cudaStreamNonBlocking);
        cudaEventCreateWithFlags(&s_fork, cudaEventDisableTiming);
        cudaEventCreateWithFlags(&s_join, cudaEventDisableTiming);
    }

    // ---- fork: CSR chain on side stream ----
    cudaEventRecord(s_fork, 0);
    cudaStreamWaitEvent(s_side, s_fork, 0);

    init_kernel  <<<(NG + 255) / 256, 256, 0, s_side>>>();
    detect_kernel<<<1, 1024, 0, s_side>>>((const unsigned*)ei);
    count_kernel <<<(NE + 255) / 256, 256, 0, s_side>>>(ei);
    scan1_kernel <<<NBLK, SCAN_BLK, 0, s_side>>>();
    scan2_kernel <<<1, 512, 0, s_side>>>();
    scan3_kernel <<<NBLK, SCAN_BLK, 0, s_side>>>();
    fill_kernel  <<<(NE + 255) / 256, 256, 0, s_side>>>(ei);
    cudaEventRecord(s_join, s_side);

    // ---- main stream: operand prep + GEMM1 (independent of CSR) ----
    x0_fp16_kernel<<<(NG * F_ / 4 + 255) / 256, 256>>>(x0);
    {
        int tot = F_ * F_ + F_ * H_ + H_ * H_;
        wt_all_kernel<<<(tot + 255) / 256, 256>>>(Wc, W1, W2);
    }
    // xw = x0 @ Wc   (fp32 out)  M=80000 N=128 K=128
    {
        dim3 grid(F_ / 128, NG / 128);
        gemm_fp16<0><<<grid, 256, SMEM_TOT_>>>(p_x016, p_wct, nullptr, p_xw, nullptr, F_, F_);
    }

    // ---- join: gather needs CSR + xw ----
    cudaStreamWaitEvent(0, s_join, 0);
    gather_kernel<<<NG / 8, 256>>>(x0, bc);

    // h1 = leaky(xres @ W1 + b1) -> fp16   M=80000 N=256 K=128
    {
        dim3 grid(H_ / 128, NG / 128);
        gemm_fp16<3><<<grid, 256, SMEM_TOT_>>>(p_xr16, p_w1t, b1, nullptr, p_h116, H_, F_);
    }

    // out = leaky(h1 @ W2 + b2) -> fp32   M=80000 N=256 K=256
    {
        dim3 grid(H_ / 128, NG / 128);
        gemm_fp16<2><<<grid, 256, SMEM_TOT_>>>(p_h116, p_w2t, b2, out, nullptr, H_, H_);
    }
}

// round 17
// speedup vs baseline: 1.8656x; 1.0542x over previous
#include <cuda_runtime.h>
#include <cuda_fp16.h>
#include <cstdint>

// Problem dims (fixed by the dataset)
#define B_  8
#define N_  10000
#define E_  160000
#define F_  128
#define H_  256
#define NG  (B_ * N_)   // 80000 total nodes
#define NE  (B_ * E_)   // 1280000 total edges
#define SCAN_BLK 256
#define NBLK ((NG + SCAN_BLK - 1) / SCAN_BLK)   // 313

// ---------------- static scratch (no allocations allowed) ----------------
__device__ __align__(16) __half g_xw16[NG * F_];   // x @ Wc (fp16, for gather)
__device__ __align__(16) __half g_x016[NG * F_];   // x0 as fp16
__device__ __align__(16) __half g_xr16[NG * F_];   // xres as fp16
__device__ __align__(16) __half g_h116[NG * H_];   // h1 as fp16
// weights transposed to [N][K] fp16: T[n*K+k] = W[k*N+n]
__device__ __align__(16) __half g_wct[F_ * F_];
__device__ __align__(16) __half g_w1t[H_ * F_];
__device__ __align__(16) __half g_w2t[H_ * H_];

__device__ int   g_cnt [NG];
__device__ float g_dinv[NG];
__device__ int   g_off [NG + 1];
__device__ int   g_cur [NG];
__device__ int   g_esrc[NE];
__device__ int   g_bsum[NBLK];
__device__ int   g_boff[NBLK];
__device__ int   g_is64;

// ================= helpers =================
__device__ __forceinline__ uint32_t smem_u32(const void* p) {
    uint32_t a;
    asm("{ .reg .u64 t; cvta.to.shared.u64 t, %1; cvt.u32.u64 %0, t; }" : "=r"(a) : "l"(p));
    return a;
}
__device__ __forceinline__ void cp16(uint32_t dst, const void* src) {
    asm volatile("cp.async.cg.shared.global [%0], [%1], 16;" :: "r"(dst), "l"(src) : "memory");
}
__device__ __forceinline__ void cpcommit() {
    asm volatile("cp.async.commit_group;" ::: "memory");
}
template <int Nw> __device__ __forceinline__ void cpwait() {
    asm volatile("cp.async.wait_group %0;" :: "n"(Nw) : "memory");
}
__device__ __forceinline__ void ldm4(uint32_t* r, uint32_t addr) {
    asm volatile("ldmatrix.sync.aligned.m8n8.x4.shared.b16 {%0,%1,%2,%3}, [%4];"
        : "=r"(r[0]), "=r"(r[1]), "=r"(r[2]), "=r"(r[3]) : "r"(addr));
}
__device__ __forceinline__ void mma_fp16(float* c, const uint32_t* a, uint32_t b0, uint32_t b1) {
    asm volatile(
        "mma.sync.aligned.m16n8k16.row.col.f32.f16.f16.f32 "
        "{%0,%1,%2,%3}, {%4,%5,%6,%7}, {%8,%9}, {%0,%1,%2,%3};"
        : "+f"(c[0]), "+f"(c[1]), "+f"(c[2]), "+f"(c[3])
        : "r"(a[0]), "r"(a[1]), "r"(a[2]), "r"(a[3]), "r"(b0), "r"(b1));
}
__device__ __forceinline__ uint32_t pack_h2(float a, float b) {
    __half2 h = __floats2half2_rn(a, b);
    return *reinterpret_cast<uint32_t*>(&h);
}

// ---------------- init (zero cnt + dtype flag) ----------------
__global__ void init_kernel() {
    int i = blockIdx.x * blockDim.x + threadIdx.x;
    if (i < NG) g_cnt[i] = 0;
    if (i == 0) g_is64 = 1;
}
// single block: checks 1024 64-bit slots; int32 buffer is 2*NE*4 B, so
// 1024*8 B is far in-bounds either way.
__global__ void detect_kernel(const unsigned* __restrict__ w) {
    int i = threadIdx.x;
    if (w[2 * i + 1] != 0u) g_is64 = 0;
}

// ---------------- CSR construction ----------------
__device__ __forceinline__ int load_edge(const void* eiv, size_t pos) {
    if (g_is64) return (int)((const long long*)eiv)[pos];
    return ((const int*)eiv)[pos];
}
__global__ void count_kernel(const void* __restrict__ eiv) {
    int idx = blockIdx.x * blockDim.x + threadIdx.x;
    if (idx >= NE) return;
    int b = idx / E_;
    int e = idx - b * E_;
    int dst = load_edge(eiv, (size_t)b * 2 * E_ + E_ + e);
    atomicAdd(&g_cnt[b * N_ + dst], 1);
}

// ---- 3-phase chip-wide scan ----
__global__ __launch_bounds__(SCAN_BLK) void scan1_kernel() {
    __shared__ int sh[SCAN_BLK];
    int i = blockIdx.x * SCAN_BLK + threadIdx.x;
    int tid = threadIdx.x;
    int c = (i < NG) ? g_cnt[i] : 0;
    sh[tid] = c;
    __syncthreads();
    int pref = c;
#pragma unroll
    for (int off = 1; off < SCAN_BLK; off <<= 1) {
        int v = (tid >= off) ? sh[tid - off] : 0;
        __syncthreads();
        pref += v;
        sh[tid] = pref;
        __syncthreads();
    }
    if (i < NG) {
        g_off[i]  = pref - c;
        g_dinv[i] = rsqrtf((float)(c + 1));
    }
    if (tid == SCAN_BLK - 1) g_bsum[blockIdx.x] = pref;
}
__global__ __launch_bounds__(512) void scan2_kernel() {
    __shared__ int sh[512];
    int tid = threadIdx.x;
    int v = (tid < NBLK) ? g_bsum[tid] : 0;
    sh[tid] = v;
    __syncthreads();
    int pref = v;
#pragma unroll
    for (int off = 1; off < 512; off <<= 1) {
        int u = (tid >= off) ? sh[tid - off] : 0;
        __syncthreads();
        pref += u;
        sh[tid] = pref;
        __syncthreads();
    }
    if (tid < NBLK) g_boff[tid] = pref - v;
    if (tid == NBLK - 1) g_off[NG] = pref;
}
__global__ __launch_bounds__(SCAN_BLK) void scan3_kernel() {
    int i = blockIdx.x * SCAN_BLK + threadIdx.x;
    if (i >= NG) return;
    int o = g_off[i] + g_boff[blockIdx.x];
    g_off[i] = o;
    g_cur[i] = o;
}

__global__ void fill_kernel(const void* __restrict__ eiv) {
    int idx = blockIdx.x * blockDim.x + threadIdx.x;
    if (idx >= NE) return;
    int b = idx / E_;
    int e = idx - b * E_;
    size_t base = (size_t)b * 2 * E_;
    int src = load_edge(eiv, base + e);
    int dst = load_edge(eiv, base + E_ + e);
    int pos = atomicAdd(&g_cur[b * N_ + dst], 1);
    g_esrc[pos] = b * N_ + src;
}

// ---------------- x0 -> fp16 ----------------
__global__ void x0_fp16_kernel(const float* __restrict__ x0) {
    int i = blockIdx.x * blockDim.x + threadIdx.x;   // over NG*F/4
    if (i >= NG * F_ / 4) return;
    float4 v = ((const float4*)x0)[i];
    uint2 o = make_uint2(pack_h2(v.x, v.y), pack_h2(v.z, v.w));
    ((uint2*)g_x016)[i] = o;
}

// ---------------- all three weight transposes -> fp16 [N][K] ---------------
__global__ void wt_all_kernel(const float* __restrict__ Wc,
                              const float* __restrict__ W1,
                              const float* __restrict__ W2) {
    int i = blockIdx.x * blockDim.x + threadIdx.x;
    const int n0 = F_ * F_;
    const int n1 = F_ * H_;
    const int n2 = H_ * H_;
    const float* W; __half* T; int K, Nn, idx;
    if (i < n0)                { W = Wc; T = g_wct; K = F_; Nn = F_; idx = i; }
    else if (i < n0 + n1)      { W = W1; T = g_w1t; K = F_; Nn = H_; idx = i - n0; }
    else if (i < n0 + n1 + n2) { W = W2; T = g_w2t; K = H_; Nn = H_; idx = i - n0 - n1; }
    else return;
    int n = idx / K, k = idx - n * K;
    T[(size_t)n * K + k] = __float2half_rn(W[(size_t)k * Nn + n]);
}

// ---------------- aggregation gather (warp per destination node) -----------
// xres = relu(agg + bc) + x0 -> fp16.  xw read as fp16 (half traffic),
// accumulated in fp32.
__global__ __launch_bounds__(256) void gather_kernel(const float* __restrict__ x0,
                                                     const float* __restrict__ bc) {
    int warp = (blockIdx.x * blockDim.x + threadIdx.x) >> 5;
    int lane = threadIdx.x & 31;
    if (warp >= NG) return;

    const uint2* xw2 = (const uint2*)g_xw16;   // 4 halves per lane
    float di = g_dinv[warp];

    uint2 u0 = xw2[(size_t)warp * 32 + lane];
    float2 s0 = __half22float2(*(__half2*)&u0.x);
    float2 s1 = __half22float2(*(__half2*)&u0.y);
    float  w0 = di * di;
    float4 acc;
    acc.x = w0 * s0.x; acc.y = w0 * s0.y; acc.z = w0 * s1.x; acc.w = w0 * s1.y;

    int e0 = g_off[warp], e1 = g_off[warp + 1];
    for (int e = e0; e < e1; e++) {
        int   s = g_esrc[e];
        float w = di * g_dinv[s];
        uint2 u = xw2[(size_t)s * 32 + lane];
        float2 f0 = __half22float2(*(__half2*)&u.x);
        float2 f1 = __half22float2(*(__half2*)&u.y);
        acc.x += w * f0.x; acc.y += w * f0.y; acc.z += w * f1.x; acc.w += w * f1.y;
    }

    float4 b4 = ((const float4*)bc)[lane];
    float4 r4 = ((const float4*)x0)[(size_t)warp * 32 + lane];
    float o0 = fmaxf(acc.x + b4.x, 0.f) + r4.x;
    float o1 = fmaxf(acc.y + b4.y, 0.f) + r4.y;
    float o2 = fmaxf(acc.z + b4.z, 0.f) + r4.z;
    float o3 = fmaxf(acc.w + b4.w, 0.f) + r4.w;

    uint2 o = make_uint2(pack_h2(o0, o1), pack_h2(o2, o3));
    ((uint2*)g_xr16)[(size_t)warp * 32 + lane] = o;
}

// ================= HMMA fp16 GEMM: k-chunk 64, 3-stage cp.async ============
// C[M,N] = act(A @ B^T + bias); A [M,K] row-major fp16, B [N,K] row-major
// fp16 (transposed weights). CTA tile 128x128, 8 warps of 64x32, smem row
// stride 144 B (odd 16B multiple -> ldmatrix conflict-free).
// EPI: 0 = fp32 out, no bias; 1 = fp16 out, no bias;
//      2 = bias+leaky -> fp32; 3 = bias+leaky -> fp16.
#define ROWB_   144
#define A_BYTES_ (128 * ROWB_)      // 18432
#define STAGE_B_ (256 * ROWB_)      // 36864
#define SMEM_TOT_ (3 * STAGE_B_)    // 110592

template <int EPI>
__global__ __launch_bounds__(256) void gemm_fp16(
    const __half* __restrict__ Ap, const __half* __restrict__ Bp,
    const float* __restrict__ bias, float* __restrict__ Cf,
    __half* __restrict__ Ch, int Nn, int Ka)
{
    extern __shared__ __align__(16) char smem[];
    const int tid  = threadIdx.x;
    const int w    = tid >> 5;
    const int lane = tid & 31;
    const int m0 = blockIdx.y * 128;
    const int n0 = blockIdx.x * 128;
    const int m0w = (w >> 2) * 64;
    const int n0w = (w & 3) * 32;

    const uint32_t sb = smem_u32(smem);

    float acc[4][4][4];
#pragma unroll
    for (int a = 0; a < 4; a++)
#pragma unroll
        for (int b = 0; b < 4; b++)
#pragma unroll
            for (int q = 0; q < 4; q++) acc[a][b][q] = 0.f;

    const int grp = lane >> 3, lr = lane & 7;
    const uint32_t aSel = (uint32_t)((m0w + (grp & 1) * 8 + lr) * ROWB_ + (grp >> 1) * 16);
    const uint32_t bSel = (uint32_t)((n0w + ((grp >> 1) & 1) * 8 + lr) * ROWB_ + (grp & 1) * 16);

    const int nk = Ka >> 6;

#define PREFETCH(kc, st)                                                          \
    {                                                                             \
        const int k0_ = (kc) << 6;                                                \
        _Pragma("unroll")                                                         \
        for (int i_ = 0; i_ < 4; i_++) {                                          \
            int c_ = tid + i_ * 256;                                              \
            int row_ = c_ >> 3, q_ = (c_ & 7) * 8;                                \
            cp16(sb + (st) * STAGE_B_ + row_ * ROWB_ + q_ * 2,                    \
                 Ap + (size_t)(m0 + row_) * Ka + k0_ + q_);                       \
            cp16(sb + (st) * STAGE_B_ + A_BYTES_ + row_ * ROWB_ + q_ * 2,         \
                 Bp + (size_t)(n0 + row_) * Ka + k0_ + q_);                       \
        }                                                                         \
        cpcommit();                                                               \
    }

    PREFETCH(0, 0);
    PREFETCH(1, 1);

    for (int kc = 0; kc < nk; kc++) {
        const int st = kc % 3;
        if (kc + 2 < nk)      { const int s2 = (kc + 2) % 3; PREFETCH(kc + 2, s2); cpwait<2>(); }
        else if (kc + 1 < nk) { cpwait<1>(); }
        else                  { cpwait<0>(); }
        __syncthreads();

        const uint32_t aBase = sb + st * STAGE_B_ + aSel;
        const uint32_t bBase = sb + st * STAGE_B_ + A_BYTES_ + bSel;
#pragma unroll
        for (int ks = 0; ks < 4; ks++) {
            uint32_t a[4][4], b[2][4];
#pragma unroll
            for (int mi = 0; mi < 4; mi++)
                ldm4(a[mi], aBase + mi * 16 * ROWB_ + ks * 32);
#pragma unroll
            for (int nj = 0; nj < 2; nj++)
                ldm4(b[nj], bBase + nj * 16 * ROWB_ + ks * 32);
#pragma unroll
            for (int mi = 0; mi < 4; mi++)
#pragma unroll
                for (int nf = 0; nf < 4; nf++)
                    mma_fp16(acc[mi][nf], a[mi],
                             b[nf >> 1][(nf & 1) * 2], b[nf >> 1][(nf & 1) * 2 + 1]);
        }
        __syncthreads();
    }
#undef PREFETCH

    const int r0 = lane >> 2;
    const int cc = (lane & 3) * 2;
#pragma unroll
    for (int mi = 0; mi < 4; mi++) {
        const int row1 = m0 + m0w + mi * 16 + r0;
        const int row2 = row1 + 8;
#pragma unroll
        for (int nf = 0; nf < 4; nf++) {
            const int col = n0 + n0w + nf * 8 + cc;
            float v0 = acc[mi][nf][0], v1 = acc[mi][nf][1];
            float v2 = acc[mi][nf][2], v3 = acc[mi][nf][3];
            if (EPI >= 2) {
                float bb0 = bias[col], bb1 = bias[col + 1];
                v0 += bb0; v1 += bb1; v2 += bb0; v3 += bb1;
                v0 = (v0 > 0.f) ? v0 : 0.01f * v0;
                v1 = (v1 > 0.f) ? v1 : 0.01f * v1;
                v2 = (v2 > 0.f) ? v2 : 0.01f * v2;
                v3 = (v3 > 0.f) ? v3 : 0.01f * v3;
            }
            if (EPI == 1 || EPI == 3) {
                *(uint32_t*)&Ch[(size_t)row1 * Nn + col] = pack_h2(v0, v1);
                *(uint32_t*)&Ch[(size_t)row2 * Nn + col] = pack_h2(v2, v3);
            } else {
                *(float2*)&Cf[(size_t)row1 * Nn + col] = make_float2(v0, v1);
                *(float2*)&Cf[(size_t)row2 * Nn + col] = make_float2(v2, v3);
            }
        }
    }
}

// ---------------- launch ----------------
extern "C" void kernel_launch(void* const* d_in, const int* in_sizes, int n_in,
                              void* d_out, int out_size) {
    const float* x0  = (const float*)d_in[0];   // [B,N,F]
    const void*  ei  = d_in[1];                 // [B,2,E] int32 OR int64
    const float* Wc  = (const float*)d_in[2];   // [F,F]
    const float* bc  = (const float*)d_in[3];   // [F]
    const float* W1  = (const float*)d_in[4];   // [F,H]
    const float* b1  = (const float*)d_in[5];   // [H]
    const float* W2  = (const float*)d_in[6];   // [H,H]
    const float* b2  = (const float*)d_in[7];   // [H]
    float*       out = (float*)d_out;           // [B,N,H]

    __half *p_xw16, *p_x016, *p_xr16, *p_h116, *p_wct, *p_w1t, *p_w2t;
    cudaGetSymbolAddress((void**)&p_xw16, g_xw16);
    cudaGetSymbolAddress((void**)&p_x016, g_x016);
    cudaGetSymbolAddress((void**)&p_xr16, g_xr16);
    cudaGetSymbolAddress((void**)&p_h116, g_h116);
    cudaGetSymbolAddress((void**)&p_wct,  g_wct);
    cudaGetSymbolAddress((void**)&p_w1t,  g_w1t);
    cudaGetSymbolAddress((void**)&p_w2t,  g_w2t);

    cudaFuncSetAttribute(gemm_fp16<1>, cudaFuncAttributeMaxDynamicSharedMemorySize, SMEM_TOT_);
    cudaFuncSetAttribute(gemm_fp16<2>, cudaFuncAttributeMaxDynamicSharedMemorySize, SMEM_TOT_);
    cudaFuncSetAttribute(gemm_fp16<3>, cudaFuncAttributeMaxDynamicSharedMemorySize, SMEM_TOT_);

    // persistent side stream + events (host resources, created once)
    static cudaStream_t s_side = nullptr;
    static cudaEvent_t  s_fork = nullptr, s_join = nullptr;
    if (!s_side) {
        cudaStreamCreateWithFlags(&s_side, cudaStreamNonBlocking);
        cudaEventCreateWithFlags(&s_fork, cudaEventDisableTiming);
        cudaEventCreateWithFlags(&s_join, cudaEventDisableTiming);
    }

    // ---- fork: CSR chain on side stream ----
    cudaEventRecord(s_fork, 0);
    cudaStreamWaitEvent(s_side, s_fork, 0);

    init_kernel  <<<(NG + 255) / 256, 256, 0, s_side>>>();
    detect_kernel<<<1, 1024, 0, s_side>>>((const unsigned*)ei);
    count_kernel <<<(NE + 255) / 256, 256, 0, s_side>>>(ei);
    scan1_kernel <<<NBLK, SCAN_BLK, 0, s_side>>>();
    scan2_kernel <<<1, 512, 0, s_side>>>();
    scan3_kernel <<<NBLK, SCAN_BLK, 0, s_side>>>();
    fill_kernel  <<<(NE + 255) / 256, 256, 0, s_side>>>(ei);
    cudaEventRecord(s_join, s_side);

    // ---- main stream: operand prep + GEMM1 (independent of CSR) ----
    x0_fp16_kernel<<<(NG * F_ / 4 + 255) / 256, 256>>>(x0);
    {
        int tot = F_ * F_ + F_ * H_ + H_ * H_;
        wt_all_kernel<<<(tot + 255) / 256, 256>>>(Wc, W1, W2);
    }
    // xw = x0 @ Wc   (fp16 out, no bias)  M=80000 N=128 K=128
    {
        dim3 grid(F_ / 128, NG / 128);
        gemm_fp16<1><<<grid, 256, SMEM_TOT_>>>(p_x016, p_wct, nullptr, nullptr, p_xw16, F_, F_);
    }

    // ---- join: gather needs CSR + xw ----
    cudaStreamWaitEvent(0, s_join, 0);
    gather_kernel<<<NG / 8, 256>>>(x0, bc);

    // h1 = leaky(xres @ W1 + b1) -> fp16   M=80000 N=256 K=128
    {
        dim3 grid(H_ / 128, NG / 128);
        gemm_fp16<3><<<grid, 256, SMEM_TOT_>>>(p_xr16, p_w1t, b1, nullptr, p_h116, H_, F_);
    }

    // out = leaky(h1 @ W2 + b2) -> fp32   M=80000 N=256 K=256
    {
        dim3 grid(H_ / 128, NG / 128);
        gemm_fp16<2><<<grid, 256, SMEM_TOT_>>>(p_h116, p_w2t, b2, out, nullptr, H_, H_);
    }
}